// round 16
// baseline (speedup 1.0000x reference)
#include <cuda_runtime.h>

// Problem constants
#define B_DIM   512
#define N_DIM   1024
#define M_DIM   128
#define OUTD    256     // X feature dim (= layer-1 target K)
#define IND     512     // hidden / output dim
#define LDW     512     // row stride of W1, W2

#define TPB        512
#define ROWS       64            // m-rows per block
#define AS_STRIDE  68            // pad: stride%4==0 (16B align), %32==4 (conflict mitigation)
#define WT_STRIDE  132           // 128 + 4
#define KP         32            // k-panel depth

#define AS_ELEMS  (256 * AS_STRIDE)
#define HS_ELEMS  (512 * AS_STRIDE)
#define WT_ELEMS  (KP * WT_STRIDE)
#define CMV_ELEMS 512
#define SMEM_BYTES ((AS_ELEMS + HS_ELEMS + WT_ELEMS + CMV_ELEMS) * 4)   // 227,840 B

// 16 FMAs of one k-step: acc[2][8] += a{0,1} * w[8]
#define FMA16()                                                        \
    acc[0][0] = fmaf(a0, w0.x, acc[0][0]);                             \
    acc[0][1] = fmaf(a0, w0.y, acc[0][1]);                             \
    acc[0][2] = fmaf(a0, w0.z, acc[0][2]);                             \
    acc[0][3] = fmaf(a0, w0.w, acc[0][3]);                             \
    acc[0][4] = fmaf(a0, w1.x, acc[0][4]);                             \
    acc[0][5] = fmaf(a0, w1.y, acc[0][5]);                             \
    acc[0][6] = fmaf(a0, w1.z, acc[0][6]);                             \
    acc[0][7] = fmaf(a0, w1.w, acc[0][7]);                             \
    acc[1][0] = fmaf(a1, w0.x, acc[1][0]);                             \
    acc[1][1] = fmaf(a1, w0.y, acc[1][1]);                             \
    acc[1][2] = fmaf(a1, w0.z, acc[1][2]);                             \
    acc[1][3] = fmaf(a1, w0.w, acc[1][3]);                             \
    acc[1][4] = fmaf(a1, w1.x, acc[1][4]);                             \
    acc[1][5] = fmaf(a1, w1.y, acc[1][5]);                             \
    acc[1][6] = fmaf(a1, w1.z, acc[1][6]);                             \
    acc[1][7] = fmaf(a1, w1.w, acc[1][7]);

// Stage a [128 i][32 k] weight panel transposed into Wt[k][i].
__device__ __forceinline__ void stage_panel(float* __restrict__ Wt,
                                            const float* __restrict__ Wg,
                                            int i0, int k0, int tid)
{
#pragma unroll
    for (int u = 0; u < 2; ++u) {
        int q  = (tid << 1) + u;       // 0..1023
        int i  = q >> 3;               // 0..127
        int kk = (q & 7) << 2;         // 0,4,...,28
        float4 w = *(const float4*)(Wg + (size_t)(i0 + i) * LDW + k0 + kk);
        Wt[(kk + 0) * WT_STRIDE + i] = w.x;
        Wt[(kk + 1) * WT_STRIDE + i] = w.y;
        Wt[(kk + 2) * WT_STRIDE + i] = w.z;
        Wt[(kk + 3) * WT_STRIDE + i] = w.w;
    }
}

__global__ void __launch_bounds__(TPB, 1)
classifier_kernel(const float* __restrict__ X,
                  const float* __restrict__ molvec,
                  const int* __restrict__ idxM,   // int32! (JAX x64-disabled downcast)
                  const float* __restrict__ W1,
                  const float* __restrict__ b1,
                  const float* __restrict__ W2,
                  const float* __restrict__ b2,
                  float* __restrict__ out)
{
    extern __shared__ float sm[];
    float* As  = sm;                  // [256][AS_STRIDE]  gathered target_x, k-major
    float* Hs  = As + AS_ELEMS;       // [512][AS_STRIDE]  hidden h, i-major
    float* Wt  = Hs + HS_ELEMS;       // [KP][WT_STRIDE]   transposed weight panel
    float* cmv = Wt + WT_ELEMS;       // [512]             b1 + molvec @ W1b^T

    const int tid  = threadIdx.x;
    const int lane = tid & 31;
    const int wid  = tid >> 5;        // 0..15
    const int b    = blockIdx.x >> 1;
    const int m0   = (blockIdx.x & 1) << 6;   // 0 or 64

    // ---- Phase A1: cmv[i] = b1[i] + sum_k molvec[b][k] * W1[i][256+k] ----
    {
        const float* mv = molvec + (size_t)b * 256 + lane * 8;
        const float4 mva = *(const float4*)mv;
        const float4 mvb = *(const float4*)(mv + 4);
#pragma unroll 4
        for (int r = 0; r < 32; ++r) {
            const int i = (wid << 5) + r;
            const float* wr = W1 + (size_t)i * LDW + 256 + lane * 8;
            const float4 wa = *(const float4*)wr;
            const float4 wb = *(const float4*)(wr + 4);
            float s = mva.x * wa.x + mva.y * wa.y + mva.z * wa.z + mva.w * wa.w
                    + mvb.x * wb.x + mvb.y * wb.y + mvb.z * wb.z + mvb.w * wb.w;
#pragma unroll
            for (int off = 16; off; off >>= 1)
                s += __shfl_xor_sync(0xffffffffu, s, off);
            if (lane == 0) cmv[i] = s + __ldg(b1 + i);
        }
    }

    // ---- Phase A2: gather As[k][r] = X[b][idx[m0+r]][k] ----
    {
        const int* idxp = idxM + (size_t)b * M_DIM + m0;
        const float* Xb = X + (size_t)b * N_DIM * OUTD;
#pragma unroll
        for (int itr = 0; itr < 8; ++itr) {
            const int lin = tid + itr * TPB;       // 0..4095
            const int r   = lin >> 6;              // 0..63
            const int k4  = (lin & 63) << 2;       // 0..252
            int idx = idxp[r];
            idx = min(max(idx, 0), N_DIM - 1);     // safety clamp (1 IMNMX)
            const float4 v = *(const float4*)(Xb + (size_t)idx * OUTD + k4);
            As[(k4 + 0) * AS_STRIDE + r] = v.x;
            As[(k4 + 1) * AS_STRIDE + r] = v.y;
            As[(k4 + 2) * AS_STRIDE + r] = v.z;
            As[(k4 + 3) * AS_STRIDE + r] = v.w;
        }
    }

    // GEMM thread mapping: 32 (m) x 16 (i); micro-tile 2m x 8i
    const int tx = tid & 31;
    const int ty = tid >> 5;
    const int m_base = tx << 1;      // 0..62
    const int i_base = ty << 3;      // 0..120

    // ---- Layer 1: Hs[i][m] = relu(As^T @ W1a^T + cmv) ----
    for (int itile = 0; itile < 4; ++itile) {
        const int i0 = itile << 7;
        float acc[2][8];
#pragma unroll
        for (int m = 0; m < 2; ++m)
#pragma unroll
            for (int j = 0; j < 8; ++j) acc[m][j] = 0.0f;

        for (int kp = 0; kp < OUTD / KP; ++kp) {       // 8 panels
            __syncthreads();
            stage_panel(Wt, W1, i0, kp * KP, tid);
            __syncthreads();
#pragma unroll
            for (int k = 0; k < KP; ++k) {
                const float* ar = As + (kp * KP + k) * AS_STRIDE + m_base;
                const float a0 = ar[0];
                const float a1 = ar[1];
                const float* wr = Wt + k * WT_STRIDE + i_base;
                const float4 w0 = *(const float4*)wr;
                const float4 w1 = *(const float4*)(wr + 4);
                FMA16();
            }
        }
#pragma unroll
        for (int j = 0; j < 8; ++j) {
            const int i = i0 + i_base + j;
            const float c = cmv[i];
            float2 h;
            h.x = fmaxf(acc[0][j] + c, 0.0f);
            h.y = fmaxf(acc[1][j] + c, 0.0f);
            *(float2*)(Hs + i * AS_STRIDE + m_base) = h;
        }
    }

    // ---- Layer 2: out = Hs^T @ W2^T + b2 ----
    float* outp = out + ((size_t)b * M_DIM + m0 + m_base) * IND;
    for (int ot = 0; ot < 4; ++ot) {
        const int o0 = ot << 7;
        float acc[2][8];
#pragma unroll
        for (int m = 0; m < 2; ++m)
#pragma unroll
            for (int j = 0; j < 8; ++j) acc[m][j] = 0.0f;

        for (int kp = 0; kp < IND / KP; ++kp) {        // 16 panels
            __syncthreads();
            stage_panel(Wt, W2, o0, kp * KP, tid);
            __syncthreads();
#pragma unroll
            for (int k = 0; k < KP; ++k) {
                const float* ar = Hs + (kp * KP + k) * AS_STRIDE + m_base;
                const float a0 = ar[0];
                const float a1 = ar[1];
                const float* wr = Wt + k * WT_STRIDE + i_base;
                const float4 w0 = *(const float4*)wr;
                const float4 w1 = *(const float4*)(wr + 4);
                FMA16();
            }
        }
        float bb[8];
#pragma unroll
        for (int j = 0; j < 8; ++j) bb[j] = __ldg(b2 + o0 + i_base + j);
#pragma unroll
        for (int m = 0; m < 2; ++m) {
            float4 lo, hi;
            lo.x = acc[m][0] + bb[0]; lo.y = acc[m][1] + bb[1];
            lo.z = acc[m][2] + bb[2]; lo.w = acc[m][3] + bb[3];
            hi.x = acc[m][4] + bb[4]; hi.y = acc[m][5] + bb[5];
            hi.z = acc[m][6] + bb[6]; hi.w = acc[m][7] + bb[7];
            *(float4*)(outp + (size_t)m * IND + o0 + i_base)     = lo;
            *(float4*)(outp + (size_t)m * IND + o0 + i_base + 4) = hi;
        }
    }
}

extern "C" void kernel_launch(void* const* d_in, const int* in_sizes, int n_in,
                              void* d_out, int out_size)
{
    const float* X      = (const float*)d_in[0];
    const float* molvec = (const float*)d_in[1];
    const int*   idxM   = (const int*)d_in[2];      // int32 per metadata
    const float* W1     = (const float*)d_in[3];
    const float* b1     = (const float*)d_in[4];
    const float* W2     = (const float*)d_in[5];
    const float* b2     = (const float*)d_in[6];
    float*       out    = (float*)d_out;

    cudaFuncSetAttribute(classifier_kernel,
                         cudaFuncAttributeMaxDynamicSharedMemorySize, SMEM_BYTES);

    classifier_kernel<<<B_DIM * 2, TPB, SMEM_BYTES>>>(
        X, molvec, idxM, W1, b1, W2, b2, out);
}

// round 17
// speedup vs baseline: 1.0007x; 1.0007x over previous
#include <cuda_runtime.h>

// Problem constants
#define B_DIM   512
#define N_DIM   1024
#define M_DIM   128
#define OUTD    256     // X feature dim (= layer-1 target K)
#define IND     512     // hidden / output dim
#define LDW     512     // row stride of W1, W2

#define TPB        512
#define ROWS       64            // m-rows per block
#define AS_STRIDE  68            // pad: stride%4==0 (16B align), %32==4 (conflict mitigation)
#define WT_STRIDE  132           // 128 + 4
#define KP         32            // k-panel depth

#define AS_ELEMS  (256 * AS_STRIDE)
#define HS_ELEMS  (512 * AS_STRIDE)
#define WT_ELEMS  (KP * WT_STRIDE)
#define CMV_ELEMS 512
#define SMEM_BYTES ((AS_ELEMS + HS_ELEMS + WT_ELEMS + CMV_ELEMS) * 4)   // 227,840 B

// 16 FMAs of one k-step: acc[2][8] += a{0,1} * w[8]
#define FMA16()                                                        \
    acc[0][0] = fmaf(a0, w0.x, acc[0][0]);                             \
    acc[0][1] = fmaf(a0, w0.y, acc[0][1]);                             \
    acc[0][2] = fmaf(a0, w0.z, acc[0][2]);                             \
    acc[0][3] = fmaf(a0, w0.w, acc[0][3]);                             \
    acc[0][4] = fmaf(a0, w1.x, acc[0][4]);                             \
    acc[0][5] = fmaf(a0, w1.y, acc[0][5]);                             \
    acc[0][6] = fmaf(a0, w1.z, acc[0][6]);                             \
    acc[0][7] = fmaf(a0, w1.w, acc[0][7]);                             \
    acc[1][0] = fmaf(a1, w0.x, acc[1][0]);                             \
    acc[1][1] = fmaf(a1, w0.y, acc[1][1]);                             \
    acc[1][2] = fmaf(a1, w0.z, acc[1][2]);                             \
    acc[1][3] = fmaf(a1, w0.w, acc[1][3]);                             \
    acc[1][4] = fmaf(a1, w1.x, acc[1][4]);                             \
    acc[1][5] = fmaf(a1, w1.y, acc[1][5]);                             \
    acc[1][6] = fmaf(a1, w1.z, acc[1][6]);                             \
    acc[1][7] = fmaf(a1, w1.w, acc[1][7]);

// Stage a [128 i][32 k] weight panel transposed into Wt[k][i].
__device__ __forceinline__ void stage_panel(float* __restrict__ Wt,
                                            const float* __restrict__ Wg,
                                            int i0, int k0, int tid)
{
#pragma unroll
    for (int u = 0; u < 2; ++u) {
        int q  = (tid << 1) + u;       // 0..1023
        int i  = q >> 3;               // 0..127
        int kk = (q & 7) << 2;         // 0,4,...,28
        float4 w = *(const float4*)(Wg + (size_t)(i0 + i) * LDW + k0 + kk);
        Wt[(kk + 0) * WT_STRIDE + i] = w.x;
        Wt[(kk + 1) * WT_STRIDE + i] = w.y;
        Wt[(kk + 2) * WT_STRIDE + i] = w.z;
        Wt[(kk + 3) * WT_STRIDE + i] = w.w;
    }
}

__global__ void __launch_bounds__(TPB, 1)
classifier_kernel(const float* __restrict__ X,
                  const float* __restrict__ molvec,
                  const int* __restrict__ idxM,   // int32! (JAX x64-disabled downcast)
                  const float* __restrict__ W1,
                  const float* __restrict__ b1,
                  const float* __restrict__ W2,
                  const float* __restrict__ b2,
                  float* __restrict__ out)
{
    extern __shared__ float sm[];
    float* As  = sm;                  // [256][AS_STRIDE]  gathered target_x, k-major
    float* Hs  = As + AS_ELEMS;       // [512][AS_STRIDE]  hidden h, i-major
    float* Wt  = Hs + HS_ELEMS;       // [KP][WT_STRIDE]   transposed weight panel
    float* cmv = Wt + WT_ELEMS;       // [512]             b1 + molvec @ W1b^T

    const int tid  = threadIdx.x;
    const int lane = tid & 31;
    const int wid  = tid >> 5;        // 0..15
    const int b    = blockIdx.x >> 1;
    const int m0   = (blockIdx.x & 1) << 6;   // 0 or 64

    // ---- Phase A1: cmv[i] = b1[i] + sum_k molvec[b][k] * W1[i][256+k] ----
    {
        const float* mv = molvec + (size_t)b * 256 + lane * 8;
        const float4 mva = *(const float4*)mv;
        const float4 mvb = *(const float4*)(mv + 4);
#pragma unroll 4
        for (int r = 0; r < 32; ++r) {
            const int i = (wid << 5) + r;
            const float* wr = W1 + (size_t)i * LDW + 256 + lane * 8;
            const float4 wa = *(const float4*)wr;
            const float4 wb = *(const float4*)(wr + 4);
            float s = mva.x * wa.x + mva.y * wa.y + mva.z * wa.z + mva.w * wa.w
                    + mvb.x * wb.x + mvb.y * wb.y + mvb.z * wb.z + mvb.w * wb.w;
#pragma unroll
            for (int off = 16; off; off >>= 1)
                s += __shfl_xor_sync(0xffffffffu, s, off);
            if (lane == 0) cmv[i] = s + __ldg(b1 + i);
        }
    }

    // ---- Phase A2: gather As[k][r] = X[b][idx[m0+r]][k] ----
    {
        const int* idxp = idxM + (size_t)b * M_DIM + m0;
        const float* Xb = X + (size_t)b * N_DIM * OUTD;
#pragma unroll
        for (int itr = 0; itr < 8; ++itr) {
            const int lin = tid + itr * TPB;       // 0..4095
            const int r   = lin >> 6;              // 0..63
            const int k4  = (lin & 63) << 2;       // 0..252
            int idx = idxp[r];
            idx = min(max(idx, 0), N_DIM - 1);     // safety clamp (1 IMNMX)
            const float4 v = *(const float4*)(Xb + (size_t)idx * OUTD + k4);
            As[(k4 + 0) * AS_STRIDE + r] = v.x;
            As[(k4 + 1) * AS_STRIDE + r] = v.y;
            As[(k4 + 2) * AS_STRIDE + r] = v.z;
            As[(k4 + 3) * AS_STRIDE + r] = v.w;
        }
    }

    // GEMM thread mapping: 32 (m) x 16 (i); micro-tile 2m x 8i
    const int tx = tid & 31;
    const int ty = tid >> 5;
    const int m_base = tx << 1;      // 0..62
    const int i_base = ty << 3;      // 0..120

    // ---- Layer 1: Hs[i][m] = relu(As^T @ W1a^T + cmv) ----
    for (int itile = 0; itile < 4; ++itile) {
        const int i0 = itile << 7;
        float acc[2][8];
#pragma unroll
        for (int m = 0; m < 2; ++m)
#pragma unroll
            for (int j = 0; j < 8; ++j) acc[m][j] = 0.0f;

        for (int kp = 0; kp < OUTD / KP; ++kp) {       // 8 panels
            __syncthreads();
            stage_panel(Wt, W1, i0, kp * KP, tid);
            __syncthreads();
#pragma unroll
            for (int k = 0; k < KP; ++k) {
                const float* ar = As + (kp * KP + k) * AS_STRIDE + m_base;
                const float a0 = ar[0];
                const float a1 = ar[1];
                const float* wr = Wt + k * WT_STRIDE + i_base;
                const float4 w0 = *(const float4*)wr;
                const float4 w1 = *(const float4*)(wr + 4);
                FMA16();
            }
        }
#pragma unroll
        for (int j = 0; j < 8; ++j) {
            const int i = i0 + i_base + j;
            const float c = cmv[i];
            float2 h;
            h.x = fmaxf(acc[0][j] + c, 0.0f);
            h.y = fmaxf(acc[1][j] + c, 0.0f);
            *(float2*)(Hs + i * AS_STRIDE + m_base) = h;
        }
    }

    // ---- Layer 2: out = Hs^T @ W2^T + b2 ----
    float* outp = out + ((size_t)b * M_DIM + m0 + m_base) * IND;
    for (int ot = 0; ot < 4; ++ot) {
        const int o0 = ot << 7;
        float acc[2][8];
#pragma unroll
        for (int m = 0; m < 2; ++m)
#pragma unroll
            for (int j = 0; j < 8; ++j) acc[m][j] = 0.0f;

        for (int kp = 0; kp < IND / KP; ++kp) {        // 16 panels
            __syncthreads();
            stage_panel(Wt, W2, o0, kp * KP, tid);
            __syncthreads();
#pragma unroll
            for (int k = 0; k < KP; ++k) {
                const float* ar = Hs + (kp * KP + k) * AS_STRIDE + m_base;
                const float a0 = ar[0];
                const float a1 = ar[1];
                const float* wr = Wt + k * WT_STRIDE + i_base;
                const float4 w0 = *(const float4*)wr;
                const float4 w1 = *(const float4*)(wr + 4);
                FMA16();
            }
        }
        float bb[8];
#pragma unroll
        for (int j = 0; j < 8; ++j) bb[j] = __ldg(b2 + o0 + i_base + j);
#pragma unroll
        for (int m = 0; m < 2; ++m) {
            float4 lo, hi;
            lo.x = acc[m][0] + bb[0]; lo.y = acc[m][1] + bb[1];
            lo.z = acc[m][2] + bb[2]; lo.w = acc[m][3] + bb[3];
            hi.x = acc[m][4] + bb[4]; hi.y = acc[m][5] + bb[5];
            hi.z = acc[m][6] + bb[6]; hi.w = acc[m][7] + bb[7];
            *(float4*)(outp + (size_t)m * IND + o0 + i_base)     = lo;
            *(float4*)(outp + (size_t)m * IND + o0 + i_base + 4) = hi;
        }
    }
}

extern "C" void kernel_launch(void* const* d_in, const int* in_sizes, int n_in,
                              void* d_out, int out_size)
{
    const float* X      = (const float*)d_in[0];
    const float* molvec = (const float*)d_in[1];
    const int*   idxM   = (const int*)d_in[2];      // int32 per metadata
    const float* W1     = (const float*)d_in[3];
    const float* b1     = (const float*)d_in[4];
    const float* W2     = (const float*)d_in[5];
    const float* b2     = (const float*)d_in[6];
    float*       out    = (float*)d_out;

    cudaFuncSetAttribute(classifier_kernel,
                         cudaFuncAttributeMaxDynamicSharedMemorySize, SMEM_BYTES);

    classifier_kernel<<<B_DIM * 2, TPB, SMEM_BYTES>>>(
        X, molvec, idxM, W1, b1, W2, b2, out);
}